// round 17
// baseline (speedup 1.0000x reference)
#include <cuda_runtime.h>
#include <cuda_bf16.h>
#include <math.h>
#include <stdint.h>

#define Bq 64
#define Nq 4096
#define Dq 256
#define Hq 512
#define ROWS 512
#define SCALEF 0.0625f
#define LN_EPS 1e-5f
#define EPS_A 1e-8f

#define TPW 2                 // tokens per warp (attend)
#define TILE_TOK 16           // tokens per block-tile
#define ATPB 16               // tiles per block -> 256 tokens/block
#define ACH (Nq/(TILE_TOK*ATPB))   // 16 chunks per batch
#define XTFLOATS (TILE_TOK*Dq)     // 4096 floats = 16KB per tile

// -------------------- scratch --------------------
__device__ float g_xln[(size_t)Bq*Nq*Dq];
__device__ float g_slots[ROWS*Dq];
__device__ float g_s[ROWS*Dq];
__device__ float g_qk[ROWS*Dq];
__device__ float g_c[ROWS];
__device__ float g_numer[ROWS*Dq];
__device__ float g_part[(size_t)ACH*ROWS*Dq];
__device__ float g_dpart[ACH*ROWS];
__device__ float g_upd[ROWS*Dq];
__device__ float g_gx[ROWS*3*Dq];
__device__ float g_gh[ROWS*3*Dq];
__device__ float g_h[ROWS*Dq];
__device__ float g_hln[ROWS*Dq];
__device__ float g_ff1[ROWS*Hq];
__device__ float g_w2t[Dq*Dq];
__device__ float g_vb[Dq];
__device__ float g_bqk[Dq];
__device__ float g_cconst[1];

__device__ __forceinline__ float dot4f(float4 a, float4 b) {
    float p = a.x*b.x;
    p = fmaf(a.y, b.y, p);
    p = fmaf(a.z, b.z, p);
    p = fmaf(a.w, b.w, p);
    return p;
}

// -------------------- LayerNorm rows of 256 --------------------
__global__ void ln_rows_kernel(const float* __restrict__ x, const float* __restrict__ w,
                               const float* __restrict__ bb, float* __restrict__ y) {
    __shared__ float sm[8];
    __shared__ float sm2[8];
    size_t row = blockIdx.x;
    int t = threadIdx.x;
    float v = x[row*Dq + t];
    float s = v;
    #pragma unroll
    for (int o = 16; o > 0; o >>= 1) s += __shfl_xor_sync(0xffffffffu, s, o);
    if ((t & 31) == 0) sm[t >> 5] = s;
    __syncthreads();
    float mean = 0.f;
    #pragma unroll
    for (int i = 0; i < 8; i++) mean += sm[i];
    mean *= (1.0f/Dq);
    float d = v - mean;
    float sq = d*d;
    #pragma unroll
    for (int o = 16; o > 0; o >>= 1) sq += __shfl_xor_sync(0xffffffffu, sq, o);
    if ((t & 31) == 0) sm2[t >> 5] = sq;
    __syncthreads();
    float var = 0.f;
    #pragma unroll
    for (int i = 0; i < 8; i++) var += sm2[i];
    var *= (1.0f/Dq);
    y[row*Dq + t] = d * rsqrtf(var + LN_EPS) * w[t] + bb[t];
}

// -------------------- LN(slots) fused with c (loop tail, iters 1..3) --------------
__global__ void lncv_kernel(const float* __restrict__ x, const float* __restrict__ w,
                            const float* __restrict__ bb, const float* __restrict__ vb,
                            const float* __restrict__ cconst,
                            float* __restrict__ y, float* __restrict__ c) {
    __shared__ float sm[8];
    __shared__ float sm2[8];
    __shared__ float sm3[8];
    size_t row = blockIdx.x;
    int t = threadIdx.x;
    float v = x[row*Dq + t];
    float s = v;
    #pragma unroll
    for (int o = 16; o > 0; o >>= 1) s += __shfl_xor_sync(0xffffffffu, s, o);
    if ((t & 31) == 0) sm[t >> 5] = s;
    __syncthreads();
    float mean = 0.f;
    #pragma unroll
    for (int i = 0; i < 8; i++) mean += sm[i];
    mean *= (1.0f/Dq);
    float d = v - mean;
    float sq = d*d;
    #pragma unroll
    for (int o = 16; o > 0; o >>= 1) sq += __shfl_xor_sync(0xffffffffu, sq, o);
    if ((t & 31) == 0) sm2[t >> 5] = sq;
    __syncthreads();
    float var = 0.f;
    #pragma unroll
    for (int i = 0; i < 8; i++) var += sm2[i];
    var *= (1.0f/Dq);
    float out = d * rsqrtf(var + LN_EPS) * w[t] + bb[t];
    y[row*Dq + t] = out;
    float p = out * vb[t];
    #pragma unroll
    for (int o = 16; o > 0; o >>= 1) p += __shfl_xor_sync(0xffffffffu, p, o);
    if ((t & 31) == 0) sm3[t >> 5] = p;
    __syncthreads();
    if (t == 0) {
        float sum = 0.f;
        #pragma unroll
        for (int i = 0; i < 8; i++) sum += sm3[i];
        c[row] = sum + cconst[0];
    }
}

// -------------------- iter-0 prologue: slots init + LN_s + c + qk matvec ----------
__global__ void __launch_bounds__(256) lncvqk_kernel(const float* __restrict__ qp,
                                                     const float* __restrict__ lsw,
                                                     const float* __restrict__ lsb,
                                                     const float* __restrict__ vb,
                                                     const float* __restrict__ cconst,
                                                     const float* __restrict__ w2t,
                                                     const float* __restrict__ bqk,
                                                     float* __restrict__ slots,
                                                     float* __restrict__ c,
                                                     float* __restrict__ qkout) {
    __shared__ __align__(16) float ss[256];
    __shared__ float sm[8];
    __shared__ float sm2[8];
    __shared__ float sm3[8];
    int row = blockIdx.x, t = threadIdx.x;
    float v = qp[(row & 7)*Dq + t];
    slots[(size_t)row*Dq + t] = v;
    float s = v;
    #pragma unroll
    for (int o = 16; o > 0; o >>= 1) s += __shfl_xor_sync(0xffffffffu, s, o);
    if ((t & 31) == 0) sm[t >> 5] = s;
    __syncthreads();
    float mean = 0.f;
    #pragma unroll
    for (int i = 0; i < 8; i++) mean += sm[i];
    mean *= (1.0f/Dq);
    float d = v - mean;
    float sq = d*d;
    #pragma unroll
    for (int o = 16; o > 0; o >>= 1) sq += __shfl_xor_sync(0xffffffffu, sq, o);
    if ((t & 31) == 0) sm2[t >> 5] = sq;
    __syncthreads();
    float var = 0.f;
    #pragma unroll
    for (int i = 0; i < 8; i++) var += sm2[i];
    var *= (1.0f/Dq);
    float out = d * rsqrtf(var + LN_EPS) * lsw[t] + lsb[t];
    ss[t] = out;
    float p = out * vb[t];
    #pragma unroll
    for (int o = 16; o > 0; o >>= 1) p += __shfl_xor_sync(0xffffffffu, p, o);
    if ((t & 31) == 0) sm3[t >> 5] = p;
    __syncthreads();
    if (t == 0) {
        float sum = 0.f;
        #pragma unroll
        for (int i = 0; i < 8; i++) sum += sm3[i];
        c[row] = sum + cconst[0];
    }
    // qk[row][t] = ss . w2t[t] + bqk[t]
    float q = 0.f;
    const float4* wr = (const float4*)(w2t + (size_t)t*Dq);
    const float4* s4 = (const float4*)ss;
    #pragma unroll 8
    for (int k4 = 0; k4 < 64; k4++) q += dot4f(wr[k4], s4[k4]);
    qkout[(size_t)row*Dq + t] = q + bqk[t];
}

// -------------------- merged weight prep: w2t tiles + vb/bqk/cconst ---------------
__global__ void __launch_bounds__(256) prep_all_kernel(const float* __restrict__ wq,
                                                       const float* __restrict__ wk,
                                                       const float* __restrict__ bq,
                                                       const float* __restrict__ bk,
                                                       float* __restrict__ w2t,
                                                       float* __restrict__ vb,
                                                       float* __restrict__ bqk,
                                                       float* __restrict__ cconst) {
    int t = threadIdx.x;
    if (blockIdx.x < 16) {
        __shared__ float As[64][68];
        __shared__ float Bs[64][68];
        int m0 = (blockIdx.x & 3) * 64, n0 = (blockIdx.x >> 2) * 64;
        int tx = t & 15, ty = t >> 4;
        float acc[4][4] = {};
        for (int e0 = 0; e0 < Dq; e0 += 64) {
            #pragma unroll
            for (int i = 0; i < 4; i++) {
                int f4 = t + i*256;
                int r = f4 >> 4, cq = f4 & 15;
                float4 va = *(const float4*)(wq + (size_t)(e0 + r)*Dq + m0 + 4*cq);
                *(float4*)&As[r][4*cq] = va;
                float4 vb4 = *(const float4*)(wk + (size_t)(e0 + r)*Dq + n0 + 4*cq);
                *(float4*)&Bs[r][4*cq] = vb4;
            }
            __syncthreads();
            #pragma unroll
            for (int kk = 0; kk < 64; kk++) {
                float nv[4], mv[4];
                #pragma unroll
                for (int i = 0; i < 4; i++) nv[i] = Bs[kk][4*ty + i];
                #pragma unroll
                for (int j = 0; j < 4; j++) mv[j] = As[kk][4*tx + j];
                #pragma unroll
                for (int i = 0; i < 4; i++)
                    #pragma unroll
                    for (int j = 0; j < 4; j++)
                        acc[i][j] = fmaf(nv[i], mv[j], acc[i][j]);
            }
            __syncthreads();
        }
        #pragma unroll
        for (int i = 0; i < 4; i++)
            #pragma unroll
            for (int j = 0; j < 4; j++)
                w2t[(size_t)(n0 + 4*ty + i)*Dq + m0 + 4*tx + j] = SCALEF * acc[i][j];
    } else {
        __shared__ float red[8][33];
        int blk = blockIdx.x - 16;
        int to = t & 31, eg = t >> 5;
        bool isB = blk >= 8;
        int t0 = (blk & 7)*32 + to;
        float p = 0.f;
        #pragma unroll 4
        for (int e = eg*32; e < eg*32 + 32; e++) {
            p = isB ? fmaf(bq[e], wk[(size_t)e*Dq + t0], p)
                    : fmaf(wq[(size_t)e*Dq + t0], bk[e], p);
        }
        red[eg][to] = p;
        __syncthreads();
        if (t < 32) {
            float s = 0.f;
            #pragma unroll
            for (int i = 0; i < 8; i++) s += red[i][t];
            (isB ? bqk : vb)[(blk & 7)*32 + t] = SCALEF * s;
        }
        if (blk == 0) {
            __syncthreads();
            float q = bq[t]*bk[t];
            #pragma unroll
            for (int o = 16; o > 0; o >>= 1) q += __shfl_xor_sync(0xffffffffu, q, o);
            if ((t & 31) == 0) red[0][t >> 5] = q;
            __syncthreads();
            if (t == 0) {
                float s = 0.f;
                #pragma unroll
                for (int i = 0; i < 8; i++) s += red[0][i];
                cconst[0] = SCALEF * s;
            }
        }
    }
}

// -------------------- GEMM 64x64, BK=64 --------------------
template<bool RELU>
__device__ __forceinline__ void gemm64_body(const float* __restrict__ A,
                                            const float* __restrict__ W,
                                            const float* __restrict__ bias,
                                            const float* __restrict__ res,
                                            float* __restrict__ C,
                                            int N, int K, int m0, int n0) {
    __shared__ float As[64][65];
    __shared__ float Bs[64][65];
    int t = threadIdx.x, tx = t & 15, ty = t >> 4;
    float acc[4][4] = {};
    for (int k0 = 0; k0 < K; k0 += 64) {
        #pragma unroll
        for (int i = 0; i < 4; i++) {
            int f4 = t + i*256;
            int r = f4 >> 4, kq = f4 & 15;
            float4 va = *(const float4*)(A + (size_t)(m0 + r)*K + k0 + 4*kq);
            As[r][4*kq + 0] = va.x; As[r][4*kq + 1] = va.y;
            As[r][4*kq + 2] = va.z; As[r][4*kq + 3] = va.w;
            float4 vb4 = *(const float4*)(W + (size_t)(n0 + r)*K + k0 + 4*kq);
            Bs[r][4*kq + 0] = vb4.x; Bs[r][4*kq + 1] = vb4.y;
            Bs[r][4*kq + 2] = vb4.z; Bs[r][4*kq + 3] = vb4.w;
        }
        __syncthreads();
        #pragma unroll
        for (int kk = 0; kk < 64; kk++) {
            float a[4], b[4];
            #pragma unroll
            for (int i = 0; i < 4; i++) a[i] = As[4*ty + i][kk];
            #pragma unroll
            for (int j = 0; j < 4; j++) b[j] = Bs[4*tx + j][kk];
            #pragma unroll
            for (int i = 0; i < 4; i++)
                #pragma unroll
                for (int j = 0; j < 4; j++)
                    acc[i][j] = fmaf(a[i], b[j], acc[i][j]);
        }
        __syncthreads();
    }
    #pragma unroll
    for (int i = 0; i < 4; i++) {
        int m = m0 + 4*ty + i;
        #pragma unroll
        for (int j = 0; j < 4; j++) {
            int n = n0 + 4*tx + j;
            float v = acc[i][j];
            if (bias) v += bias[n];
            if (RELU) v = fmaxf(v, 0.f);
            if (res)  v += res[(size_t)m*N + n];
            C[(size_t)m*N + n] = v;
        }
    }
}

template<bool RELU>
__global__ void __launch_bounds__(256) gemm64_kernel(const float* __restrict__ A,
                                                     const float* __restrict__ W,
                                                     const float* __restrict__ bias,
                                                     const float* __restrict__ res,
                                                     float* __restrict__ C,
                                                     int N, int K) {
    gemm64_body<RELU>(A, W, bias, res, C, N, K, blockIdx.y*64, blockIdx.x*64);
}

__global__ void __launch_bounds__(256) gemm64_dual_kernel(const float* __restrict__ A0,
                                                          const float* __restrict__ W0,
                                                          const float* __restrict__ b0,
                                                          float* __restrict__ C0,
                                                          const float* __restrict__ A1,
                                                          const float* __restrict__ W1,
                                                          const float* __restrict__ b1,
                                                          float* __restrict__ C1,
                                                          int N, int K) {
    if (blockIdx.z == 0)
        gemm64_body<false>(A0, W0, b0, nullptr, C0, N, K, blockIdx.y*64, blockIdx.x*64);
    else
        gemm64_body<false>(A1, W1, b1, nullptr, C1, N, K, blockIdx.y*64, blockIdx.x*64);
}

// -------------------- attend v5: cp.async double-buffered pipeline ----------------
__global__ void __launch_bounds__(256, 2) attend5_kernel(const float* __restrict__ xln,
                                                         const float* __restrict__ qk,
                                                         const float* __restrict__ cc,
                                                         float* __restrict__ part,
                                                         float* __restrict__ dpart) {
    __shared__ __align__(16) float xbuf[2][XTFLOATS];   // 32KB; red overlaid post-loop
    __shared__ __align__(16) float4 qk4[512];           // 8KB
    __shared__ float sds[64];
    __shared__ __align__(16) float a_sh[8][16];
    int b = blockIdx.y;
    int t = threadIdx.x, w = t >> 5, l = t & 31;
    {
        const float4* src = (const float4*)(qk + (size_t)b*8*Dq);
        qk4[t]       = src[t];
        qk4[t + 256] = src[t + 256];
    }
    float cr = cc[b*8 + (l & 7)];
    float accB[64];
    #pragma unroll
    for (int i = 0; i < 64; i++) accB[i] = 0.f;
    float dsl = 0.f;

    const float* xblk = xln + ((size_t)b*Nq + (size_t)blockIdx.x*(TILE_TOK*ATPB))*Dq;

    // prefetch tile 0 into buf 0
    {
        uint32_t d0 = (uint32_t)__cvta_generic_to_shared(&xbuf[0][0]) + (uint32_t)t*16u;
        const char* s0 = (const char*)xblk + t*16;
        #pragma unroll
        for (int i = 0; i < 4; i++)
            asm volatile("cp.async.cg.shared.global [%0], [%1], 16;\n"
                         :: "r"(d0 + i*4096u), "l"(s0 + i*4096));
        asm volatile("cp.async.commit_group;\n" ::: "memory");
    }

    for (int tile = 0; tile < ATPB; tile++) {
        __syncthreads();   // all warps done with the buffer we are about to overwrite
        if (tile + 1 < ATPB) {
            uint32_t d0 = (uint32_t)__cvta_generic_to_shared(&xbuf[(tile + 1) & 1][0])
                          + (uint32_t)t*16u;
            const char* s0 = (const char*)(xblk + (size_t)(tile + 1)*XTFLOATS) + t*16;
            #pragma unroll
            for (int i = 0; i < 4; i++)
                asm volatile("cp.async.cg.shared.global [%0], [%1], 16;\n"
                             :: "r"(d0 + i*4096u), "l"(s0 + i*4096));
            asm volatile("cp.async.commit_group;\n" ::: "memory");
            asm volatile("cp.async.wait_group 1;\n" ::: "memory");
        } else {
            asm volatile("cp.async.wait_group 0;\n" ::: "memory");
        }
        __syncthreads();   // tile's data visible to all warps

        const float* xt = &xbuf[tile & 1][0];
        float4 xa[TPW], xb[TPW];
        #pragma unroll
        for (int j = 0; j < TPW; j++) {
            xa[j] = *(const float4*)(xt + (w*TPW + j)*Dq + 4*l);
            xb[j] = *(const float4*)(xt + (w*TPW + j)*Dq + 128 + 4*l);
        }
        // phase A: 16 (tok,slot) partial logits per lane
        float v[16];
        #pragma unroll
        for (int s = 0; s < 8; s++) {
            float4 qa = qk4[s*64 + l];
            float4 qb = qk4[s*64 + 32 + l];
            #pragma unroll
            for (int j = 0; j < TPW; j++) {
                float p = xa[j].x * qa.x;
                p = fmaf(xa[j].y, qa.y, p);
                p = fmaf(xa[j].z, qa.z, p);
                p = fmaf(xa[j].w, qa.w, p);
                p = fmaf(xb[j].x, qb.x, p);
                p = fmaf(xb[j].y, qb.y, p);
                p = fmaf(xb[j].z, qb.z, p);
                p = fmaf(xb[j].w, qb.w, p);
                v[j*8 + s] = p;
            }
        }
        #pragma unroll
        for (int i = 0; i < 16; i++)
            v[i] += __shfl_xor_sync(0xffffffffu, v[i], 16);
        #pragma unroll
        for (int half = 8; half >= 1; half >>= 1) {
            int hi = l & half;
            #pragma unroll
            for (int i = 0; i < half; i++) {
                float send = hi ? v[i] : v[i + half];
                float keep = hi ? v[i + half] : v[i];
                v[i] = keep + __shfl_xor_sync(0xffffffffu, send, half);
            }
        }
        float lg = v[0] + cr;
        float m = lg;
        #pragma unroll
        for (int o = 1; o <= 4; o <<= 1) m = fmaxf(m, __shfl_xor_sync(0xffffffffu, m, o));
        float e = __expf(lg - m);
        float sum = e;
        #pragma unroll
        for (int o = 1; o <= 4; o <<= 1) sum += __shfl_xor_sync(0xffffffffu, sum, o);
        float a = fmaf(e, __fdividef(1.f, sum), EPS_A);
        dsl += a;
        __syncwarp();
        if (l < 16) a_sh[w][l] = a;
        __syncwarp();
        #pragma unroll
        for (int j = 0; j < TPW; j++) {
            float4 a0 = *(const float4*)&a_sh[w][j*8];
            float4 a1 = *(const float4*)&a_sh[w][j*8 + 4];
            float av[8] = {a0.x, a0.y, a0.z, a0.w, a1.x, a1.y, a1.z, a1.w};
            #pragma unroll
            for (int s = 0; s < 8; s++) {
                accB[s*8 + 0] = fmaf(av[s], xa[j].x, accB[s*8 + 0]);
                accB[s*8 + 1] = fmaf(av[s], xa[j].y, accB[s*8 + 1]);
                accB[s*8 + 2] = fmaf(av[s], xa[j].z, accB[s*8 + 2]);
                accB[s*8 + 3] = fmaf(av[s], xa[j].w, accB[s*8 + 3]);
                accB[s*8 + 4] = fmaf(av[s], xb[j].x, accB[s*8 + 4]);
                accB[s*8 + 5] = fmaf(av[s], xb[j].y, accB[s*8 + 5]);
                accB[s*8 + 6] = fmaf(av[s], xb[j].z, accB[s*8 + 6]);
                accB[s*8 + 7] = fmaf(av[s], xb[j].w, accB[s*8 + 7]);
            }
        }
    }
    // denom (halves duplicated; xor-8 folds the two tokens)
    dsl += __shfl_xor_sync(0xffffffffu, dsl, 8);
    if (l < 8) sds[w*8 + l] = dsl;
    // cross-warp reduce accB into red (overlaid on xbuf[0]; round 0 assigns)
    float* red = &xbuf[0][0];
    for (int r = 0; r < 8; r++) {
        __syncthreads();
        if (w == r) {
            #pragma unroll
            for (int s = 0; s < 8; s++) {
                #pragma unroll
                for (int q = 0; q < 4; q++) {
                    if (r == 0) {
                        red[s*256 + 4*l + q]       = accB[s*8 + q];
                        red[s*256 + 128 + 4*l + q] = accB[s*8 + 4 + q];
                    } else {
                        red[s*256 + 4*l + q]       += accB[s*8 + q];
                        red[s*256 + 128 + 4*l + q] += accB[s*8 + 4 + q];
                    }
                }
            }
        }
    }
    __syncthreads();
    size_t pbase = ((size_t)blockIdx.x*ROWS + b*8)*Dq;
    #pragma unroll
    for (int i = 0; i < 8; i++) part[pbase + i*256 + t] = red[i*256 + t];
    if (t < 8) {
        float sum = 0.f;
        #pragma unroll
        for (int ww = 0; ww < 8; ww++) sum += sds[ww*8 + t];
        dpart[blockIdx.x*ROWS + b*8 + t] = sum;
    }
}

// -------------------- reduce partials over chunks and normalize --------------------
__global__ void reduce_norm_kernel(const float* __restrict__ part,
                                   const float* __restrict__ dpart,
                                   float* __restrict__ numer) {
    int row = blockIdx.x, t = threadIdx.x;
    float s = 0.f, dn = 0.f;
    #pragma unroll
    for (int c = 0; c < ACH; c++) {
        s  += part[((size_t)c*ROWS + row)*Dq + t];
        dn += dpart[c*ROWS + row];
    }
    numer[(size_t)row*Dq + t] = s / dn;
}

// -------------------- GRU cell fused with LN_ff --------------------
__global__ void gruln_kernel(const float* __restrict__ gx, const float* __restrict__ gh,
                             const float* __restrict__ slots,
                             const float* __restrict__ lw, const float* __restrict__ lb,
                             float* __restrict__ h, float* __restrict__ hln) {
    __shared__ float sm[8];
    __shared__ float sm2[8];
    int row = blockIdx.x, t = threadIdx.x;
    const float* gxr = gx + (size_t)row*768;
    const float* ghr = gh + (size_t)row*768;
    float r = 1.f/(1.f + expf(-(gxr[t]       + ghr[t])));
    float z = 1.f/(1.f + expf(-(gxr[256 + t] + ghr[256 + t])));
    float n = tanhf(gxr[512 + t] + r*ghr[512 + t]);
    float hv = (1.f - z)*n + z*slots[(size_t)row*Dq + t];
    h[(size_t)row*Dq + t] = hv;
    float s = hv;
    #pragma unroll
    for (int o = 16; o > 0; o >>= 1) s += __shfl_xor_sync(0xffffffffu, s, o);
    if ((t & 31) == 0) sm[t >> 5] = s;
    __syncthreads();
    float mean = 0.f;
    #pragma unroll
    for (int i = 0; i < 8; i++) mean += sm[i];
    mean *= (1.0f/Dq);
    float d = hv - mean;
    float sq = d*d;
    #pragma unroll
    for (int o = 16; o > 0; o >>= 1) sq += __shfl_xor_sync(0xffffffffu, sq, o);
    if ((t & 31) == 0) sm2[t >> 5] = sq;
    __syncthreads();
    float var = 0.f;
    #pragma unroll
    for (int i = 0; i < 8; i++) var += sm2[i];
    var *= (1.0f/Dq);
    hln[(size_t)row*Dq + t] = d * rsqrtf(var + LN_EPS) * lw[t] + lb[t];
}

// -------------------- host --------------------
extern "C" void kernel_launch(void* const* d_in, const int* in_sizes, int n_in,
                              void* d_out, int out_size) {
    (void)in_sizes; (void)n_in; (void)out_size;
    const float* inputs    = (const float*)d_in[0];
    const float* query_pos = (const float*)d_in[1];
    const float* wq   = (const float*)d_in[2];
    const float* bq   = (const float*)d_in[3];
    const float* wk   = (const float*)d_in[4];
    const float* bk   = (const float*)d_in[5];
    const float* wv   = (const float*)d_in[6];
    const float* bv   = (const float*)d_in[7];
    const float* w_ih = (const float*)d_in[8];
    const float* b_ih = (const float*)d_in[9];
    const float* w_hh = (const float*)d_in[10];
    const float* b_hh = (const float*)d_in[11];
    const float* w1   = (const float*)d_in[12];
    const float* b1   = (const float*)d_in[13];
    const float* w2   = (const float*)d_in[14];
    const float* b2   = (const float*)d_in[15];
    const float* ln_in_w = (const float*)d_in[16];
    const float* ln_in_b = (const float*)d_in[17];
    const float* ln_s_w  = (const float*)d_in[18];
    const float* ln_s_b  = (const float*)d_in[19];
    const float* ln_ff_w = (const float*)d_in[20];
    const float* ln_ff_b = (const float*)d_in[21];
    float* out = (float*)d_out;

    float *xln, *slots, *s, *qkb, *c, *numer, *part, *dpart, *upd, *gx, *gh, *h, *hln, *ff1;
    float *w2t, *vb, *bqk, *cconst;
    cudaGetSymbolAddress((void**)&xln,   g_xln);
    cudaGetSymbolAddress((void**)&slots, g_slots);
    cudaGetSymbolAddress((void**)&s,     g_s);
    cudaGetSymbolAddress((void**)&qkb,   g_qk);
    cudaGetSymbolAddress((void**)&c,     g_c);
    cudaGetSymbolAddress((void**)&numer, g_numer);
    cudaGetSymbolAddress((void**)&part,  g_part);
    cudaGetSymbolAddress((void**)&dpart, g_dpart);
    cudaGetSymbolAddress((void**)&upd,   g_upd);
    cudaGetSymbolAddress((void**)&gx,    g_gx);
    cudaGetSymbolAddress((void**)&gh,    g_gh);
    cudaGetSymbolAddress((void**)&h,     g_h);
    cudaGetSymbolAddress((void**)&hln,   g_hln);
    cudaGetSymbolAddress((void**)&ff1,   g_ff1);
    cudaGetSymbolAddress((void**)&w2t,   g_w2t);
    cudaGetSymbolAddress((void**)&vb,    g_vb);
    cudaGetSymbolAddress((void**)&bqk,   g_bqk);
    cudaGetSymbolAddress((void**)&cconst,g_cconst);

    // prologue (attend is the 4th launch -> captured by ncu)
    prep_all_kernel<<<32, 256>>>(wq, wk, bq, bk, w2t, vb, bqk, cconst);
    ln_rows_kernel<<<Bq*Nq, 256>>>(inputs, ln_in_w, ln_in_b, xln);
    lncvqk_kernel<<<ROWS, 256>>>(query_pos, ln_s_w, ln_s_b, vb, cconst, w2t, bqk,
                                 slots, c, qkb);

    for (int it = 0; it < 4; it++) {
        float* slots_out = (it == 3) ? out : slots;
        attend5_kernel<<<dim3(ACH, Bq), 256>>>(xln, qkb, c, part, dpart);
        reduce_norm_kernel<<<ROWS, 256>>>(part, dpart, numer);
        gemm64_kernel<false><<<dim3(4, 8), 256>>>(numer, wv, bv, nullptr, upd, Dq, Dq);
        gemm64_dual_kernel<<<dim3(12, 8, 2), 256>>>(upd, w_ih, b_ih, gx,
                                                    slots, w_hh, b_hh, gh, 3*Dq, Dq);
        gruln_kernel<<<ROWS, 256>>>(gx, gh, slots, ln_ff_w, ln_ff_b, h, hln);
        gemm64_kernel<true ><<<dim3(8, 8), 256>>>(hln, w1, b1, nullptr, ff1, Hq, Dq);
        gemm64_kernel<false><<<dim3(4, 8), 256>>>(ff1, w2, b2, h, slots_out, Dq, Hq);
        if (it < 3) {
            lncv_kernel<<<ROWS, 256>>>(slots, ln_s_w, ln_s_b, vb, cconst, s, c);
            gemm64_kernel<false><<<dim3(4, 8), 256>>>(s, w2t, bqk, nullptr, qkb, Dq, Dq);
        }
    }
}